// round 8
// baseline (speedup 1.0000x reference)
#include <cuda_runtime.h>
#include <cuda_bf16.h>
#include <cstdint>

#define HW   1024
#define CD   128
#define EPSF 1e-8f
#define TQ   4          // q-tiles per CTA

// Normalized features, bf16 hi/lo split, pixel-major:
// g_feat[view][p][0..127]=hi, [128..255]=lo   (512 B per pixel row)
__device__ __nv_bfloat16 g_feat[32 * HW * 256];

// ---------------------------------------------------------------------------
__device__ __forceinline__ uint32_t smem_u32(const void* p) {
    uint32_t a;
    asm("{ .reg .u64 t; cvta.to.shared.u64 t, %1; cvt.u32.u64 %0, t; }" : "=r"(a) : "l"(p));
    return a;
}

#define CP_ASYNC(s, g) \
    asm volatile("cp.async.cg.shared.global [%0], [%1], 16;" :: "r"(s), "l"(g))
#define CP_COMMIT() asm volatile("cp.async.commit_group;" ::: "memory")
#define CP_WAIT0()  asm volatile("cp.async.wait_group 0;" ::: "memory")

#define LDSM4(r, a) \
    asm volatile("ldmatrix.sync.aligned.m8n8.x4.shared.b16 {%0,%1,%2,%3}, [%4];" \
        : "=r"((r)[0]), "=r"((r)[1]), "=r"((r)[2]), "=r"((r)[3]) : "r"(a))

#define MMA(d, a, b0v, b1v)                                                  \
    asm volatile(                                                            \
        "mma.sync.aligned.m16n8k16.row.col.f32.bf16.bf16.f32 "               \
        "{%0,%1,%2,%3}, {%4,%5,%6,%7}, {%8,%9}, {%0,%1,%2,%3};\n"            \
        : "+f"((d)[0]), "+f"((d)[1]), "+f"((d)[2]), "+f"((d)[3])             \
        : "r"((a)[0]), "r"((a)[1]), "r"((a)[2]), "r"((a)[3]),                \
          "r"(b0v), "r"(b1v))

// 5-bit rotate for G-buffer swizzle (row/col/drain all ~conflict-free)
#define ROT5(v) (((((v) & 31) & 3) << 3) | (((v) & 31) >> 2))

// ---------------------------------------------------------------------------
// Kernel 1: L2-normalize per pixel, split to bf16 hi/lo, write pixel-major
// ---------------------------------------------------------------------------
__global__ __launch_bounds__(256) void norm_split_kernel(const float* __restrict__ x) {
    __shared__ uint32_t tile[8][33 * 32];
    int w = threadIdx.x >> 5, l = threadIdx.x & 31;
    int gp = blockIdx.x * 256 + w * 32 + l;        // global pixel over 32 views
    int view = gp >> 10, p = gp & 1023;
    const float* xp = x + (size_t)view * (CD * HW) + p;

    float s = 0.f;
#pragma unroll 8
    for (int c = 0; c < CD; ++c) { float v = xp[c << 10]; s += v * v; }
    float inv = 1.f / (sqrtf(s) + EPSF);

    __nv_bfloat16* ob = g_feat + (size_t)(gp - l) * 256;   // warp's base pixel row

    for (int cb = 0; cb < 4; ++cb) {
#pragma unroll
        for (int ci = 0; ci < 32; ++ci) {
            float v = xp[(cb * 32 + ci) << 10] * inv;
            __nv_bfloat16 h = __float2bfloat16(v);
            __nv_bfloat16 lo = __float2bfloat16(v - __bfloat162float(h));
            tile[w][ci * 33 + l] = (uint32_t)__bfloat16_as_ushort(h)
                                 | ((uint32_t)__bfloat16_as_ushort(lo) << 16);
        }
        __syncwarp();
#pragma unroll
        for (int rr = 0; rr < 32; ++rr) {
            uint32_t v = tile[w][l * 33 + rr];
            __nv_bfloat16* row = ob + (size_t)rr * 256 + cb * 32 + l;
            row[0]   = __ushort_as_bfloat16((unsigned short)(v & 0xFFFF));
            row[128] = __ushort_as_bfloat16((unsigned short)(v >> 16));
        }
        __syncwarp();
    }
}

// ---------------------------------------------------------------------------
// Kernel 2: persistent-q HMMA GEMM over the 48 unique view pairs.
// CTA = (pair z, p-tile, q-group of 4). Tile 128x128, warp 64x32, kc=16,
// 2-stage cp.async. After each tile: acc -> smem G (64KB, rot-swizzled);
// the 128KB of stores (direct + transposed twin) flush in 8 slices
// interleaved into the NEXT tile's k-loop, hiding STG behind MMA.
// smem: [stage0 16K][stage1 16K][G 64K] = 96KB, 2 CTAs/SM.
// ---------------------------------------------------------------------------
#define STAGE16 16384

__constant__ int c_pi[6] = {0, 0, 0, 1, 1, 2};
__constant__ int c_pj[6] = {1, 2, 3, 2, 3, 3};

__global__ __launch_bounds__(256, 2) void corr_gemm4(float* __restrict__ out) {
    extern __shared__ char smem[];
    uint32_t sb = smem_u32(smem);
    float* Gf = (float*)(smem + 2 * STAGE16);

    const int tid = threadIdx.x;
    const int w = tid >> 5, l = tid & 31;
    const int wm = w >> 2, wn = w & 3;          // warp grid 2x4
    const int lo16 = l & 15, hi2 = l >> 4;
    const int g = l >> 2, tg = l & 3;

    const int qg = blockIdx.x;                  // 0..1  -> q-tiles qg*4 .. +3
    const int p0 = blockIdx.y * 128;
    const int z  = blockIdx.z;                  // 0..47
    const int b  = z / 6, u = z % 6;
    const int i  = c_pi[u], j = c_pj[u];
    const int idx1 = b * 12 + i * 3 + (j - 1);
    const int idx2 = b * 12 + j * 3 + i;

    const char* AfB = (const char*)g_feat + (size_t)(b * 4 + j) * HW * 512 + (size_t)p0 * 512;
    const char* BfB = (const char*)g_feat + (size_t)(b * 4 + i) * HW * 512;
    float* o1 = out + (size_t)idx1 * (HW * HW);
    float* o2 = out + (size_t)idx2 * (HW * HW);

    float acc[4][4][4];
#pragma unroll
    for (int mt = 0; mt < 4; ++mt)
#pragma unroll
        for (int nt = 0; nt < 4; ++nt)
#pragma unroll
            for (int e = 0; e < 4; ++e) acc[mt][nt][e] = 0.f;

    // ---- stage loader: 1024 16B chunks (A 512 + B 512), 4 per thread ----
    auto load_stage = [&](int s1) {
        int t2 = s1 >> 3, kcg = s1 & 7;
        uint32_t sbase = sb + (uint32_t)(s1 & 1) * STAGE16;
        const char* Af2 = AfB + kcg * 32;
        const char* Bf2 = BfB + (size_t)(qg * TQ + t2) * 128 * 512 + kcg * 32;
#pragma unroll
        for (int it = 0; it < 4; ++it) {
            int t = it * 256 + tid;
            int region = t >> 9, uu = t & 511;
            int m = uu >> 2, half = (uu >> 1) & 1, c = uu & 1;
            uint32_t soff = (uint32_t)region * 8192u + (uint32_t)half * 4096u
                          + (uint32_t)(m * 32 + ((c ^ ((m >> 2) & 1)) << 4));
            const char* gp2 = (region ? Bf2 : Af2) + (size_t)m * 512 + half * 256 + c * 16;
            CP_ASYNC(sbase + soff, gp2);
        }
    };

    // ---- flush one 1/8 slice of the pending tile's stores from G ----
    auto flush_chunk = [&](int f, int tprev) {
        int qp0 = (qg * TQ + tprev) * 128;
#pragma unroll
        for (int rr = 0; rr < 2; ++rr) {              // direct: out[idx1]
            int r = f * 16 + w * 2 + rr;
            float v0 = Gf[r * 128 + ((4 * l + 0) ^ ROT5(r))];
            float v1 = Gf[r * 128 + ((4 * l + 1) ^ ROT5(r))];
            float v2 = Gf[r * 128 + ((4 * l + 2) ^ ROT5(r))];
            float v3 = Gf[r * 128 + ((4 * l + 3) ^ ROT5(r))];
            *(float4*)&o1[(size_t)(p0 + r) * HW + qp0 + 4 * l] =
                make_float4(v0, v1, v2, v3);
        }
#pragma unroll
        for (int rr = 0; rr < 2; ++rr) {              // transposed: out[idx2]
            int n = f * 16 + w * 2 + rr;
#pragma unroll
            for (int m0 = 0; m0 < 128; m0 += 32) {
                float v = Gf[(m0 + l) * 128 + (n ^ ROT5(m0 + l))];
                o2[(size_t)(qp0 + n) * HW + p0 + m0 + l] = v;
            }
        }
    };

    load_stage(0);
    CP_COMMIT();

    const int s_end = TQ * 8;
    for (int s = 0; s < s_end; ++s) {
        CP_WAIT0();
        __syncthreads();
        if (s + 1 < s_end) { load_stage(s + 1); CP_COMMIT(); }

        // ---- compute one k16 step on stage s&1 ----
        {
            uint32_t st = sb + (uint32_t)(s & 1) * STAGE16;
            const int ch = hi2;
            uint32_t ah[4][4], al[4][4], bb[2][4];
            uint32_t swb[2];
#pragma unroll
            for (int mt = 0; mt < 4; ++mt) {
                int m = wm * 64 + mt * 16 + lo16;
                uint32_t sw = (uint32_t)(m * 32 + ((ch ^ ((m >> 2) & 1)) << 4));
                LDSM4(ah[mt], st + sw);
                LDSM4(al[mt], st + 4096 + sw);
            }
#pragma unroll
            for (int np = 0; np < 2; ++np) {
                int n = wn * 32 + np * 16 + lo16;
                swb[np] = (uint32_t)(n * 32 + ((ch ^ ((n >> 2) & 1)) << 4));
                LDSM4(bb[np], st + 8192 + swb[np]);   // B_hi
            }
#pragma unroll
            for (int mt = 0; mt < 4; ++mt)
#pragma unroll
                for (int nt = 0; nt < 4; ++nt)
                    MMA(acc[mt][nt], ah[mt], bb[nt >> 1][nt & 1], bb[nt >> 1][2 + (nt & 1)]);
#pragma unroll
            for (int mt = 0; mt < 4; ++mt)
#pragma unroll
                for (int nt = 0; nt < 4; ++nt)
                    MMA(acc[mt][nt], al[mt], bb[nt >> 1][nt & 1], bb[nt >> 1][2 + (nt & 1)]);
#pragma unroll
            for (int np = 0; np < 2; ++np)
                LDSM4(bb[np], st + 12288 + swb[np]);  // B_lo
#pragma unroll
            for (int mt = 0; mt < 4; ++mt)
#pragma unroll
                for (int nt = 0; nt < 4; ++nt)
                    MMA(acc[mt][nt], ah[mt], bb[nt >> 1][nt & 1], bb[nt >> 1][2 + (nt & 1)]);
        }

        // ---- interleaved store flush of previous tile ----
        if (s >= 8) flush_chunk(s & 7, (s >> 3) - 1);

        // ---- tile boundary: drain acc -> G ----
        if ((s & 7) == 7) {
            __syncthreads();          // all flush reads of old G done
#pragma unroll
            for (int mt = 0; mt < 4; ++mt)
#pragma unroll
                for (int nt = 0; nt < 4; ++nt)
#pragma unroll
                    for (int e = 0; e < 4; ++e) {
                        int m = wm * 64 + mt * 16 + g + 8 * (e >> 1);
                        int n = wn * 32 + nt * 8 + tg * 2 + (e & 1);
                        Gf[m * 128 + (n ^ ROT5(m))] = acc[mt][nt][e];
                        acc[mt][nt][e] = 0.f;
                    }
        }
    }

    // ---- final tile's stores (exposed) ----
    __syncthreads();
#pragma unroll
    for (int f = 0; f < 8; ++f) flush_chunk(f, TQ - 1);
}

// ---------------------------------------------------------------------------
extern "C" void kernel_launch(void* const* d_in, const int* in_sizes, int n_in,
                              void* d_out, int out_size) {
    const float* x = (const float*)d_in[0];
    float* out = (float*)d_out;

    norm_split_kernel<<<128, 256>>>(x);

    int smem_sz = 2 * STAGE16 + 65536;
    cudaFuncSetAttribute(corr_gemm4, cudaFuncAttributeMaxDynamicSharedMemorySize, smem_sz);
    dim3 grid(8 / TQ, 8, 48);
    corr_gemm4<<<grid, 256, smem_sz>>>(out);
}

// round 9
// speedup vs baseline: 1.4587x; 1.4587x over previous
#include <cuda_runtime.h>
#include <cuda_bf16.h>
#include <cstdint>

#define HW   1024
#define CD   128
#define EPSF 1e-8f
#define TQ   4          // q-tiles per CTA
#define STAGE_B 32768

// Normalized features, bf16 hi/lo split, pixel-major:
// g_feat[view][p][0..127]=hi, [128..255]=lo   (512 B per pixel row)
__device__ __nv_bfloat16 g_feat[32 * HW * 256];

// ---------------------------------------------------------------------------
__device__ __forceinline__ uint32_t smem_u32(const void* p) {
    uint32_t a;
    asm("{ .reg .u64 t; cvta.to.shared.u64 t, %1; cvt.u32.u64 %0, t; }" : "=r"(a) : "l"(p));
    return a;
}

#define CP_ASYNC(s, g) \
    asm volatile("cp.async.cg.shared.global [%0], [%1], 16;" :: "r"(s), "l"(g))
#define CP_COMMIT() asm volatile("cp.async.commit_group;" ::: "memory")
#define CP_WAIT0()  asm volatile("cp.async.wait_group 0;" ::: "memory")

#define LDSM4(r, a) \
    asm volatile("ldmatrix.sync.aligned.m8n8.x4.shared.b16 {%0,%1,%2,%3}, [%4];" \
        : "=r"((r)[0]), "=r"((r)[1]), "=r"((r)[2]), "=r"((r)[3]) : "r"(a))

#define MMA(d, a, b0v, b1v)                                                  \
    asm volatile(                                                            \
        "mma.sync.aligned.m16n8k16.row.col.f32.bf16.bf16.f32 "               \
        "{%0,%1,%2,%3}, {%4,%5,%6,%7}, {%8,%9}, {%0,%1,%2,%3};\n"            \
        : "+f"((d)[0]), "+f"((d)[1]), "+f"((d)[2]), "+f"((d)[3])             \
        : "r"((a)[0]), "r"((a)[1]), "r"((a)[2]), "r"((a)[3]),                \
          "r"(b0v), "r"(b1v))

// 5-bit rotate swizzle for the G buffer (drain / row-read / col-read all
// bank-conflict-free)
#define ROT5(v) ((((v) & 3) << 3) | (((v) & 31) >> 2))

// ---------------------------------------------------------------------------
// Kernel 1: L2-normalize per pixel, split to bf16 hi/lo, write pixel-major
// ---------------------------------------------------------------------------
__global__ __launch_bounds__(256) void norm_split_kernel(const float* __restrict__ x) {
    __shared__ uint32_t tile[8][33 * 32];
    int w = threadIdx.x >> 5, l = threadIdx.x & 31;
    int gp = blockIdx.x * 256 + w * 32 + l;        // global pixel over 32 views
    int view = gp >> 10, p = gp & 1023;
    const float* xp = x + (size_t)view * (CD * HW) + p;

    float s = 0.f;
#pragma unroll 8
    for (int c = 0; c < CD; ++c) { float v = xp[c << 10]; s += v * v; }
    float inv = 1.f / (sqrtf(s) + EPSF);

    __nv_bfloat16* ob = g_feat + (size_t)(gp - l) * 256;   // warp's base pixel row

    for (int cb = 0; cb < 4; ++cb) {
#pragma unroll
        for (int ci = 0; ci < 32; ++ci) {
            float v = xp[(cb * 32 + ci) << 10] * inv;
            __nv_bfloat16 h = __float2bfloat16(v);
            __nv_bfloat16 lo = __float2bfloat16(v - __bfloat162float(h));
            tile[w][ci * 33 + l] = (uint32_t)__bfloat16_as_ushort(h)
                                 | ((uint32_t)__bfloat16_as_ushort(lo) << 16);
        }
        __syncwarp();
#pragma unroll
        for (int rr = 0; rr < 32; ++rr) {
            uint32_t v = tile[w][l * 33 + rr];
            __nv_bfloat16* row = ob + (size_t)rr * 256 + cb * 32 + l;
            row[0]   = __ushort_as_bfloat16((unsigned short)(v & 0xFFFF));
            row[128] = __ushort_as_bfloat16((unsigned short)(v >> 16));
        }
        __syncwarp();
    }
}

// ---------------------------------------------------------------------------
// Kernel 2: persistent-q HMMA GEMM over 48 unique view pairs.
// CTA = (pair, p-tile, q-group of TQ=4 tiles). Tile 128x128, warp 64x32,
// kc=32 (R7 mainloop), 2-stage cp.async, ONE sync per chunk.
// After each tile the acc drains into smem G (64KB, ROT5 swizzle); the 128KB
// of stores (direct + transposed twin) flush in 4 slices interleaved into the
// NEXT tile's 4 k-chunks, hiding STG behind MMA. Only the last tile's flush
// is exposed. smem = 2*32KB stages + 64KB G = 128KB, 1 CTA/SM.
// ---------------------------------------------------------------------------
__constant__ int c_pi[6] = {0, 0, 0, 1, 1, 2};
__constant__ int c_pj[6] = {1, 2, 3, 2, 3, 3};

__global__ __launch_bounds__(256, 1) void corr_gemm5(float* __restrict__ out) {
    extern __shared__ char smem[];
    uint32_t sb = smem_u32(smem);
    float* Gf = (float*)(smem + 2 * STAGE_B);

    const int tid = threadIdx.x;
    const int w = tid >> 5, l = tid & 31;
    const int wm = w >> 2, wn = w & 3;          // warp grid 2x4
    const int lo16 = l & 15, hi2 = l >> 4;
    const int g = l >> 2, tg = l & 3;
    const uint32_t rotl = ROT5(l);

    const int qg = blockIdx.x;                  // 0..1 -> q-tiles qg*4..+3
    const int p0 = blockIdx.y * 128;
    const int z  = blockIdx.z;                  // 0..47
    const int b  = z / 6, u = z % 6;
    const int i  = c_pi[u], j = c_pj[u];
    const int idx1 = b * 12 + i * 3 + (j - 1);
    const int idx2 = b * 12 + j * 3 + i;

    const char* AfB = (const char*)g_feat + (size_t)(b * 4 + j) * HW * 512 + (size_t)p0 * 512;
    const char* BfB = (const char*)g_feat + (size_t)(b * 4 + i) * HW * 512;
    float* o1 = out + (size_t)idx1 * (HW * HW);
    float* o2 = out + (size_t)idx2 * (HW * HW);

    float acc[4][4][4];
#pragma unroll
    for (int mt = 0; mt < 4; ++mt)
#pragma unroll
        for (int nt = 0; nt < 4; ++nt)
#pragma unroll
            for (int e = 0; e < 4; ++e) acc[mt][nt][e] = 0.f;

    // ---- stage loader: 2048 16B chunks (A 1024 + B 1024), 8 per thread ----
    auto load_stage = [&](int s1) {
        int t2 = s1 >> 2, kcg = s1 & 3;
        uint32_t sbase = sb + (uint32_t)(s1 & 1) * STAGE_B;
        const char* Af2 = AfB + kcg * 64;
        const char* Bf2 = BfB + (size_t)(qg * TQ + t2) * 128 * 512 + kcg * 64;
#pragma unroll
        for (int it = 0; it < 4; ++it) {
            int c = it * 256 + tid;
            int m = c >> 3, half = (c >> 2) & 1, ch = c & 3;
            uint32_t soff = half * 8192u + (uint32_t)((m * 4 + (ch ^ ((m >> 1) & 3))) << 4);
            size_t goff = (size_t)m * 512 + half * 256 + ch * 16;
            CP_ASYNC(sbase + soff,         Af2 + goff);
            CP_ASYNC(sbase + 16384 + soff, Bf2 + goff);
        }
    };

    // ---- flush one 1/4 slice (32 rows + 32 cols) of pending tile ----
    auto flush_slice = [&](int f, int qt) {
        int qp0 = (qg * TQ + qt) * 128;
        // direct: out[idx1] rows r
#pragma unroll
        for (int rr = 0; rr < 4; ++rr) {
            int r = f * 32 + w * 4 + rr;
            uint32_t rot = ROT5(r);
#pragma unroll
            for (int cc = 0; cc < 4; ++cc) {
                float v = Gf[r * 128 + ((l + 32 * cc) ^ rot)];
                o1[(size_t)(p0 + r) * HW + qp0 + 32 * cc + l] = v;
            }
        }
        // transposed: out[idx2] rows n (read G columns)
#pragma unroll
        for (int rr = 0; rr < 4; ++rr) {
            int n = f * 32 + w * 4 + rr;
#pragma unroll
            for (int mm = 0; mm < 4; ++mm) {
                int m = mm * 32 + l;
                float v = Gf[m * 128 + (n ^ rotl)];
                o2[(size_t)(qp0 + n) * HW + p0 + m] = v;
            }
        }
    };

    load_stage(0);
    CP_COMMIT();

    const int s_end = TQ * 4;
    for (int s = 0; s < s_end; ++s) {
        CP_WAIT0();
        __syncthreads();
        if (s + 1 < s_end) { load_stage(s + 1); CP_COMMIT(); }

        // ---- compute one k32 chunk on stage s&1 (R7 mainloop verbatim) ----
        {
            uint32_t st = sb + (uint32_t)(s & 1) * STAGE_B;
#pragma unroll
            for (int ks = 0; ks < 2; ++ks) {
                const int ch = ks * 2 + hi2;

                uint32_t ah[4][4], al[4][4], bb[2][4], swb[2];
#pragma unroll
                for (int mt = 0; mt < 4; ++mt) {
                    int m = wm * 64 + mt * 16 + lo16;
                    uint32_t sw = (uint32_t)((m * 4 + (ch ^ ((m >> 1) & 3))) << 4);
                    LDSM4(ah[mt], st + sw);
                    LDSM4(al[mt], st + 8192 + sw);
                }
#pragma unroll
                for (int np = 0; np < 2; ++np) {
                    int n = wn * 32 + np * 16 + lo16;
                    swb[np] = (uint32_t)((n * 4 + (ch ^ ((n >> 1) & 3))) << 4);
                    LDSM4(bb[np], st + 16384 + swb[np]);  // B_hi
                }
#pragma unroll
                for (int mt = 0; mt < 4; ++mt)
#pragma unroll
                    for (int nt = 0; nt < 4; ++nt)
                        MMA(acc[mt][nt], ah[mt], bb[nt >> 1][nt & 1], bb[nt >> 1][2 + (nt & 1)]);
#pragma unroll
                for (int mt = 0; mt < 4; ++mt)
#pragma unroll
                    for (int nt = 0; nt < 4; ++nt)
                        MMA(acc[mt][nt], al[mt], bb[nt >> 1][nt & 1], bb[nt >> 1][2 + (nt & 1)]);
#pragma unroll
                for (int np = 0; np < 2; ++np)
                    LDSM4(bb[np], st + 24576 + swb[np]);  // B_lo
#pragma unroll
                for (int mt = 0; mt < 4; ++mt)
#pragma unroll
                    for (int nt = 0; nt < 4; ++nt)
                        MMA(acc[mt][nt], ah[mt], bb[nt >> 1][nt & 1], bb[nt >> 1][2 + (nt & 1)]);
            }
        }

        // ---- interleaved store flush of previous tile (hidden behind MMA) ----
        if (s >= 4) flush_slice(s & 3, (s >> 2) - 1);

        // ---- tile boundary: drain acc -> G (after all flush reads of old G) ----
        if ((s & 3) == 3) {
            __syncthreads();
#pragma unroll
            for (int mt = 0; mt < 4; ++mt)
#pragma unroll
                for (int nt = 0; nt < 4; ++nt)
#pragma unroll
                    for (int e = 0; e < 4; ++e) {
                        int m = wm * 64 + mt * 16 + g + 8 * (e >> 1);
                        int n = wn * 32 + nt * 8 + tg * 2 + (e & 1);
                        Gf[m * 128 + (n ^ ROT5(m))] = acc[mt][nt][e];
                        acc[mt][nt][e] = 0.f;
                    }
        }
    }

    // ---- last tile's flush (exposed) ----
    __syncthreads();
#pragma unroll
    for (int f = 0; f < 4; ++f) flush_slice(f, TQ - 1);
}

// ---------------------------------------------------------------------------
extern "C" void kernel_launch(void* const* d_in, const int* in_sizes, int n_in,
                              void* d_out, int out_size) {
    const float* x = (const float*)d_in[0];
    float* out = (float*)d_out;

    norm_split_kernel<<<128, 256>>>(x);

    int smem_sz = 2 * STAGE_B + 65536;   // 128 KB
    cudaFuncSetAttribute(corr_gemm5, cudaFuncAttributeMaxDynamicSharedMemorySize, smem_sz);
    dim3 grid(8 / TQ, 8, 48);
    corr_gemm5<<<grid, 256, smem_sz>>>(out);
}

// round 10
// speedup vs baseline: 2.0575x; 1.4105x over previous
#include <cuda_runtime.h>
#include <cuda_bf16.h>
#include <cstdint>

#define HW   1024
#define CD   128
#define EPSF 1e-8f
#define STAGE_B 24576   // A(16KB) + B(8KB) per kc=32 stage

// Normalized features, bf16 hi/lo split, pixel-major:
// g_feat[view][p][0..127]=hi, [128..255]=lo   (512 B per pixel row)
__device__ __nv_bfloat16 g_feat[32 * HW * 256];

// ---------------------------------------------------------------------------
__device__ __forceinline__ uint32_t smem_u32(const void* p) {
    uint32_t a;
    asm("{ .reg .u64 t; cvta.to.shared.u64 t, %1; cvt.u32.u64 %0, t; }" : "=r"(a) : "l"(p));
    return a;
}

#define CP_ASYNC(s, g) \
    asm volatile("cp.async.cg.shared.global [%0], [%1], 16;" :: "r"(s), "l"(g))
#define CP_COMMIT() asm volatile("cp.async.commit_group;" ::: "memory")
#define CP_WAIT0()  asm volatile("cp.async.wait_group 0;" ::: "memory")

#define LDSM4(r, a) \
    asm volatile("ldmatrix.sync.aligned.m8n8.x4.shared.b16 {%0,%1,%2,%3}, [%4];" \
        : "=r"((r)[0]), "=r"((r)[1]), "=r"((r)[2]), "=r"((r)[3]) : "r"(a))

#define MMA(d, a, b0v, b1v)                                                  \
    asm volatile(                                                            \
        "mma.sync.aligned.m16n8k16.row.col.f32.bf16.bf16.f32 "               \
        "{%0,%1,%2,%3}, {%4,%5,%6,%7}, {%8,%9}, {%0,%1,%2,%3};\n"            \
        : "+f"((d)[0]), "+f"((d)[1]), "+f"((d)[2]), "+f"((d)[3])             \
        : "r"((a)[0]), "r"((a)[1]), "r"((a)[2]), "r"((a)[3]),                \
          "r"(b0v), "r"(b1v))

// ---------------------------------------------------------------------------
// Kernel 1: L2-normalize per pixel, split to bf16 hi/lo, write pixel-major
// ---------------------------------------------------------------------------
__global__ __launch_bounds__(256) void norm_split_kernel(const float* __restrict__ x) {
    __shared__ uint32_t tile[8][33 * 32];
    int w = threadIdx.x >> 5, l = threadIdx.x & 31;
    int gp = blockIdx.x * 256 + w * 32 + l;        // global pixel over 32 views
    int view = gp >> 10, p = gp & 1023;
    const float* xp = x + (size_t)view * (CD * HW) + p;

    float s = 0.f;
#pragma unroll 8
    for (int c = 0; c < CD; ++c) { float v = xp[c << 10]; s += v * v; }
    float inv = 1.f / (sqrtf(s) + EPSF);

    __nv_bfloat16* ob = g_feat + (size_t)(gp - l) * 256;   // warp's base pixel row

    for (int cb = 0; cb < 4; ++cb) {
#pragma unroll
        for (int ci = 0; ci < 32; ++ci) {
            float v = xp[(cb * 32 + ci) << 10] * inv;
            __nv_bfloat16 h = __float2bfloat16(v);
            __nv_bfloat16 lo = __float2bfloat16(v - __bfloat162float(h));
            tile[w][ci * 33 + l] = (uint32_t)__bfloat16_as_ushort(h)
                                 | ((uint32_t)__bfloat16_as_ushort(lo) << 16);
        }
        __syncwarp();
#pragma unroll
        for (int rr = 0; rr < 32; ++rr) {
            uint32_t v = tile[w][l * 33 + rr];
            __nv_bfloat16* row = ob + (size_t)rr * 256 + cb * 32 + l;
            row[0]   = __ushort_as_bfloat16((unsigned short)(v & 0xFFFF));
            row[128] = __ushort_as_bfloat16((unsigned short)(v >> 16));
        }
        __syncwarp();
    }
}

// ---------------------------------------------------------------------------
// Kernel 2: HMMA GEMM over 48 unique view pairs; CTA tile 128x64 (4 warps,
// warp 64x32), kc=32, 2-stage cp.async, one sync per chunk. Each CTA writes
// its G tile direct to out[idx1] and transposed (per-warp swizzled smem) to
// out[idx2]. smem 48KB -> 4 CTAs/SM for cross-CTA phase overlap.
// Stage layout: [A_hi 8K][A_lo 8K][B_hi 4K][B_lo 4K].
// ---------------------------------------------------------------------------
__constant__ int c_pi[6] = {0, 0, 0, 1, 1, 2};
__constant__ int c_pj[6] = {1, 2, 3, 2, 3, 3};

__global__ __launch_bounds__(128, 4) void corr_gemm6(float* __restrict__ out) {
    extern __shared__ char smem[];
    uint32_t sb = smem_u32(smem);
    const int tid = threadIdx.x;
    const int w = tid >> 5, l = tid & 31;
    const int wm = w >> 1, wn = w & 1;          // warp grid 2x2
    const int lo16 = l & 15, hi2 = l >> 4;
    const int g = l >> 2, tg = l & 3;

    const int q0 = blockIdx.x * 64;
    const int p0 = blockIdx.y * 128;
    const int z  = blockIdx.z;                  // 0..47
    const int b  = z / 6, u = z % 6;
    const int i  = c_pi[u], j = c_pj[u];
    const int idx1 = b * 12 + i * 3 + (j - 1);
    const int idx2 = b * 12 + j * 3 + i;

    const char* Af = (const char*)g_feat + (size_t)(b * 4 + j) * HW * 512 + (size_t)p0 * 512;
    const char* Bf = (const char*)g_feat + (size_t)(b * 4 + i) * HW * 512 + (size_t)q0 * 512;

    float acc[4][4][4];
#pragma unroll
    for (int mt = 0; mt < 4; ++mt)
#pragma unroll
        for (int nt = 0; nt < 4; ++nt)
#pragma unroll
            for (int e = 0; e < 4; ++e) acc[mt][nt][e] = 0.f;

    // ---- stage loader: 1536 16B chunks (A 1024 + B 512), 12 per thread ----
    auto load_stage = [&](int kc) {
        uint32_t sbase = sb + (uint32_t)(kc & 1) * STAGE_B;
        const char* Af2 = Af + kc * 64;
        const char* Bf2 = Bf + kc * 64;
#pragma unroll
        for (int it = 0; it < 12; ++it) {
            int c = it * 128 + tid;             // 0..1535
            if (c < 1024) {                     // A region (it 0..7)
                int m = c >> 3, half = (c >> 2) & 1, ch = c & 3;
                uint32_t soff = half * 8192u
                              + (uint32_t)((m * 4 + (ch ^ ((m >> 1) & 3))) << 4);
                CP_ASYNC(sbase + soff, Af2 + (size_t)m * 512 + half * 256 + ch * 16);
            } else {                            // B region (it 8..11)
                int u2 = c - 1024;
                int m = u2 >> 3, half = (u2 >> 2) & 1, ch = u2 & 3;
                uint32_t soff = 16384u + half * 4096u
                              + (uint32_t)((m * 4 + (ch ^ ((m >> 1) & 3))) << 4);
                CP_ASYNC(sbase + soff, Bf2 + (size_t)m * 512 + half * 256 + ch * 16);
            }
        }
    };

    load_stage(0);
    CP_COMMIT();

    for (int kc = 0; kc < 4; ++kc) {
        CP_WAIT0();
        __syncthreads();
        if (kc < 3) { load_stage(kc + 1); CP_COMMIT(); }

        uint32_t st = sb + (uint32_t)(kc & 1) * STAGE_B;
#pragma unroll
        for (int ks = 0; ks < 2; ++ks) {
            const int ch = ks * 2 + hi2;

            uint32_t ah[4][4], al[4][4], bb[2][4], swb[2];
#pragma unroll
            for (int mt = 0; mt < 4; ++mt) {
                int m = wm * 64 + mt * 16 + lo16;
                uint32_t sw = (uint32_t)((m * 4 + (ch ^ ((m >> 1) & 3))) << 4);
                LDSM4(ah[mt], st + sw);
                LDSM4(al[mt], st + 8192 + sw);
            }
#pragma unroll
            for (int np = 0; np < 2; ++np) {
                int n = wn * 32 + np * 16 + lo16;
                swb[np] = (uint32_t)((n * 4 + (ch ^ ((n >> 1) & 3))) << 4);
                LDSM4(bb[np], st + 16384 + swb[np]);  // B_hi
            }
#pragma unroll
            for (int mt = 0; mt < 4; ++mt)
#pragma unroll
                for (int nt = 0; nt < 4; ++nt)
                    MMA(acc[mt][nt], ah[mt], bb[nt >> 1][nt & 1], bb[nt >> 1][2 + (nt & 1)]);
#pragma unroll
            for (int mt = 0; mt < 4; ++mt)
#pragma unroll
                for (int nt = 0; nt < 4; ++nt)
                    MMA(acc[mt][nt], al[mt], bb[nt >> 1][nt & 1], bb[nt >> 1][2 + (nt & 1)]);
#pragma unroll
            for (int np = 0; np < 2; ++np)
                LDSM4(bb[np], st + 20480 + swb[np]);  // B_lo
#pragma unroll
            for (int mt = 0; mt < 4; ++mt)
#pragma unroll
                for (int nt = 0; nt < 4; ++nt)
                    MMA(acc[mt][nt], ah[mt], bb[nt >> 1][nt & 1], bb[nt >> 1][2 + (nt & 1)]);
        }
    }

    // ---- epilogue 1: direct fp32 float2 stores to out[idx1] ----
    {
        float* op = out + (size_t)idx1 * (HW * HW);
#pragma unroll
        for (int mt = 0; mt < 4; ++mt) {
#pragma unroll
            for (int nt = 0; nt < 4; ++nt) {
                int row = p0 + wm * 64 + mt * 16 + g;
                int col = q0 + wn * 32 + nt * 8 + tg * 2;
                *(float2*)&op[(size_t)row * HW + col] =
                    make_float2(acc[mt][nt][0], acc[mt][nt][1]);
                *(float2*)&op[(size_t)(row + 8) * HW + col] =
                    make_float2(acc[mt][nt][2], acc[mt][nt][3]);
            }
        }
    }

    // ---- epilogue 2: transposed tile to out[idx2] via swizzled smem ----
    // tw regions alias the stages -> must sync before reuse
    __syncthreads();
    {
        float* tw = (float*)smem + w * 2048;   // per-warp 8KB: G[n][m], n<32, m<64
#pragma unroll
        for (int mt = 0; mt < 4; ++mt)
#pragma unroll
            for (int nt = 0; nt < 4; ++nt)
#pragma unroll
                for (int e = 0; e < 4; ++e) {
                    int n = nt * 8 + tg * 2 + (e & 1);
                    int m = mt * 16 + g + 8 * (e >> 1);
                    tw[n * 64 + (m ^ ((n & 6) << 2))] = acc[mt][nt][e];
                }
        __syncwarp();

        float* op = out + (size_t)idx2 * (HW * HW);
        const float2* tw2 = (const float2*)tw;
#pragma unroll
        for (int n = 0; n < 32; ++n) {
            float2 v = tw2[n * 32 + (l ^ ((n & 6) << 1))];   // (G[n][2l], G[n][2l+1])
            *(float2*)&op[(size_t)(q0 + wn * 32 + n) * HW + p0 + wm * 64 + 2 * l] = v;
        }
    }
}

// ---------------------------------------------------------------------------
extern "C" void kernel_launch(void* const* d_in, const int* in_sizes, int n_in,
                              void* d_out, int out_size) {
    const float* x = (const float*)d_in[0];
    float* out = (float*)d_out;

    norm_split_kernel<<<128, 256>>>(x);

    int smem_sz = 2 * STAGE_B;   // 48 KB
    cudaFuncSetAttribute(corr_gemm6, cudaFuncAttributeMaxDynamicSharedMemorySize, smem_sz);
    dim3 grid(16, 8, 48);
    corr_gemm6<<<grid, 128, smem_sz>>>(out);
}